// round 17
// baseline (speedup 1.0000x reference)
#include <cuda_runtime.h>

// x: (4, 32, 512, 512) fp32 ; bias: (1, 32, 1, 1) fp32
// out: [G1 | G2 | G3], each (4, 32, 512, 512) fp32
//
// G1[h,w] = (h>=1 && w>=1) ? exp(-(x[h-1,w-1]-x[h,w])^2) + bias : bias
// G2[h,w] = (w>=1)          ? exp(-(x[h,  w-1]-x[h,w])^2) + bias : bias
// G3[h,w] = (h<H-1 && w>=1) ? exp(-(x[h+1,w-1]-x[h,w])^2) + bias : bias
//
// Phase-separated 3-kernel variant: each kernel produces one gate, so the
// DRAM controller sees near-unidirectional (write-dominated) traffic per
// phase instead of a permanently mixed 1R:3W stream. Kernel order: G2
// (streams x into L2), then G1 and G3 (x mostly L2-resident -> pure-write
// phases). Tests whether the 76%-busy plateau is R/W turnaround loss.

#define H   512
#define WV  128           // float4 per row
#define N4  8388608u      // float4 per gate tensor (4*32*512*512/4)

// ---------- G2: horizontal neighbor (cur row only) ----------
__global__ __launch_bounds__(256) void gate2_kernel(
    const float* __restrict__ x,
    const float* __restrict__ bias,
    float* __restrict__ out)     // -> G2 region
{
    const unsigned idx = blockIdx.x * 256u + threadIdx.x;
    const unsigned v = idx & (WV - 1);
    const unsigned c = (idx >> 16) & 31u;
    const float bi = __ldg(&bias[c]);
    const bool vs = (v > 0);
    const unsigned dv = vs ? 1u : 0u;

    const float4 cur4 = reinterpret_cast<const float4*>(x)[idx];
    const float  lc   = __ldg(&x[(idx << 2) - dv]);

    const float cur[4] = {cur4.x, cur4.y, cur4.z, cur4.w};
    const float lf[4]  = {lc, cur4.x, cur4.y, cur4.z};

    float g[4];
#pragma unroll
    for (int k = 0; k < 4; ++k) {
        const bool wok = vs || (k > 0);
        float e = lf[k] - cur[k];
        g[k] = wok ? __expf(-e * e) + bi : bi;
    }
    __stcs(&reinterpret_cast<float4*>(out)[idx], make_float4(g[0], g[1], g[2], g[3]));
}

// ---------- G1: diagonal (up row + cur row) ----------
__global__ __launch_bounds__(256) void gate1_kernel(
    const float* __restrict__ x,
    const float* __restrict__ bias,
    float* __restrict__ out)     // -> G1 region
{
    const unsigned idx = blockIdx.x * 256u + threadIdx.x;
    const unsigned v = idx & (WV - 1);
    const unsigned h = (idx >> 7) & (H - 1);
    const unsigned c = (idx >> 16) & 31u;
    const float bi = __ldg(&bias[c]);
    const bool hup = (h > 0);
    const bool vs  = (v > 0);
    const unsigned iu = hup ? idx - WV : idx;
    const unsigned dv = vs ? 1u : 0u;

    const float4 cur4 = reinterpret_cast<const float4*>(x)[idx];
    const float4 u4   = reinterpret_cast<const float4*>(x)[iu];
    const float  lu   = __ldg(&x[(iu << 2) - dv]);

    const float cur[4] = {cur4.x, cur4.y, cur4.z, cur4.w};
    const float up[4]  = {lu, u4.x, u4.y, u4.z};

    float g[4];
#pragma unroll
    for (int k = 0; k < 4; ++k) {
        const bool wok = vs || (k > 0);
        float e = up[k] - cur[k];
        g[k] = (hup && wok) ? __expf(-e * e) + bi : bi;
    }
    __stcs(&reinterpret_cast<float4*>(out)[idx], make_float4(g[0], g[1], g[2], g[3]));
}

// ---------- G3: anti-diagonal (down row + cur row) ----------
__global__ __launch_bounds__(256) void gate3_kernel(
    const float* __restrict__ x,
    const float* __restrict__ bias,
    float* __restrict__ out)     // -> G3 region
{
    const unsigned idx = blockIdx.x * 256u + threadIdx.x;
    const unsigned v = idx & (WV - 1);
    const unsigned h = (idx >> 7) & (H - 1);
    const unsigned c = (idx >> 16) & 31u;
    const float bi = __ldg(&bias[c]);
    const bool hdn = (h < H - 1);
    const bool vs  = (v > 0);
    const unsigned id = hdn ? idx + WV : idx;
    const unsigned dv = vs ? 1u : 0u;

    const float4 cur4 = reinterpret_cast<const float4*>(x)[idx];
    const float4 d4   = reinterpret_cast<const float4*>(x)[id];
    const float  ld   = __ldg(&x[(id << 2) - dv]);

    const float cur[4] = {cur4.x, cur4.y, cur4.z, cur4.w};
    const float dn[4]  = {ld, d4.x, d4.y, d4.z};

    float g[4];
#pragma unroll
    for (int k = 0; k < 4; ++k) {
        const bool wok = vs || (k > 0);
        float e = dn[k] - cur[k];
        g[k] = (hdn && wok) ? __expf(-e * e) + bi : bi;
    }
    __stcs(&reinterpret_cast<float4*>(out)[idx], make_float4(g[0], g[1], g[2], g[3]));
}

extern "C" void kernel_launch(void* const* d_in, const int* in_sizes, int n_in,
                              void* d_out, int out_size) {
    const float* x    = (const float*)d_in[0];
    const float* bias = (const float*)d_in[1];
    float* out = (float*)d_out;

    const long long total_vec = (long long)in_sizes[0] / 4;   // 8,388,608
    const int threads = 256;
    const int blocks = (int)((total_vec + threads - 1) / threads);

    // G2 first (single-row reads warm x into L2), then G1, G3.
    gate2_kernel<<<blocks, threads>>>(x, bias, out + (size_t)N4 * 4);
    gate1_kernel<<<blocks, threads>>>(x, bias, out);
    gate3_kernel<<<blocks, threads>>>(x, bias, out + (size_t)N4 * 8);
}